// round 2
// baseline (speedup 1.0000x reference)
#include <cuda_runtime.h>
#include <math.h>

#define BATCH   8
#define SEQLEN  4096
#define DIM     512
#define MROWS   (BATCH * SEQLEN)   // 32768

// ---- static scratch (no allocations allowed in kernel_launch) ----
__device__ float g_a [(size_t)MROWS * DIM];   // 64 MB  a_coef
__device__ float g_b [(size_t)MROWS * DIM];   // 64 MB  b_coef
__device__ float g_hs[(size_t)MROWS * DIM];   // 64 MB  scan output
__device__ float g_W1[1024 * DIM];            //  2 MB  interleaved [Wg;B]

// ---------------------------------------------------------------------------
// Build interleaved weight: row 2h = Wg[h,:], row 2h+1 = B[h,:]
// so that a GEMM against g_W1 yields (gate_logit, xB) in adjacent columns.
// ---------------------------------------------------------------------------
__global__ void prep_w1_kernel(const float* __restrict__ Wg,
                               const float* __restrict__ B)
{
    int idx = blockIdx.x * blockDim.x + threadIdx.x;
    if (idx < 1024 * DIM) {
        int r = idx / DIM;
        int k = idx - r * DIM;
        int h = r >> 1;
        g_W1[idx] = (r & 1) ? B[h * DIM + k] : Wg[h * DIM + k];
    }
}

// ---------------------------------------------------------------------------
// SGEMM mainloop: accumulate acc[8][8] += A[row0:+128, :K] * W[col0:+128, :K]^T
// A: MxK row-major, W: NxK row-major (NT GEMM). BM=BN=128, BK=16, 256 threads.
// ---------------------------------------------------------------------------
__device__ __forceinline__ void gemm_mainloop(
    const float* __restrict__ A, const float* __restrict__ W, int K,
    int row0, int col0, float acc[8][8],
    float (*As)[128], float (*Ws)[128])
{
    const int tid = threadIdx.x;
    const int tx  = tid & 15;
    const int ty  = tid >> 4;

    for (int k0 = 0; k0 < K; k0 += 16) {
        // Load 128x16 tiles of A and W (each: 512 float4 / 256 threads = 2 iters)
        #pragma unroll
        for (int it = 0; it < 2; ++it) {
            int v  = it * 256 + tid;   // vector index 0..511
            int m  = v >> 2;           // row within tile (4 float4 per row)
            int kv = v & 3;            // which float4 in the row
            float4 av = *reinterpret_cast<const float4*>(
                A + (size_t)(row0 + m) * K + k0 + kv * 4);
            As[kv * 4 + 0][m] = av.x;
            As[kv * 4 + 1][m] = av.y;
            As[kv * 4 + 2][m] = av.z;
            As[kv * 4 + 3][m] = av.w;
            float4 wv = *reinterpret_cast<const float4*>(
                W + (size_t)(col0 + m) * K + k0 + kv * 4);
            Ws[kv * 4 + 0][m] = wv.x;
            Ws[kv * 4 + 1][m] = wv.y;
            Ws[kv * 4 + 2][m] = wv.z;
            Ws[kv * 4 + 3][m] = wv.w;
        }
        __syncthreads();

        #pragma unroll
        for (int kk = 0; kk < 16; ++kk) {
            float af[8], wf[8];
            *reinterpret_cast<float4*>(&af[0]) =
                *reinterpret_cast<const float4*>(&As[kk][ty * 8 + 0]);
            *reinterpret_cast<float4*>(&af[4]) =
                *reinterpret_cast<const float4*>(&As[kk][ty * 8 + 4]);
            *reinterpret_cast<float4*>(&wf[0]) =
                *reinterpret_cast<const float4*>(&Ws[kk][tx * 8 + 0]);
            *reinterpret_cast<float4*>(&wf[4]) =
                *reinterpret_cast<const float4*>(&Ws[kk][tx * 8 + 4]);
            #pragma unroll
            for (int i = 0; i < 8; ++i)
                #pragma unroll
                for (int j = 0; j < 8; ++j)
                    acc[i][j] = fmaf(af[i], wf[j], acc[i][j]);
        }
        __syncthreads();
    }
}

// ---------------------------------------------------------------------------
// Stage 1: raw = x @ [Wg;B interleaved]^T  (M=32768, N=1024, K=512)
// Epilogue: g = clip(sigmoid(raw_even)); a = 1 - g*(1-A); b = g*(raw_odd + bh)
// ---------------------------------------------------------------------------
__global__ __launch_bounds__(256) void stage1_kernel(
    const float* __restrict__ x,
    const float* __restrict__ Avec,
    const float* __restrict__ bias_h)
{
    __shared__ float As[16][128];
    __shared__ float Ws[16][128];
    float acc[8][8];
    #pragma unroll
    for (int i = 0; i < 8; ++i)
        #pragma unroll
        for (int j = 0; j < 8; ++j) acc[i][j] = 0.f;

    const int row0 = blockIdx.y * 128;
    const int col0 = blockIdx.x * 128;
    gemm_mainloop(x, g_W1, DIM, row0, col0, acc, As, Ws);

    const int tx = threadIdx.x & 15;
    const int ty = threadIdx.x >> 4;
    const int cn = col0 + tx * 8;   // even-aligned

    #pragma unroll
    for (int i = 0; i < 8; ++i) {
        const int m = row0 + ty * 8 + i;
        #pragma unroll
        for (int j = 0; j < 8; j += 2) {
            const int n = cn + j;           // even: gate logit column
            const int h = n >> 1;
            float z  = acc[i][j];
            float gg = 1.0f / (1.0f + __expf(-z));
            gg = fminf(fmaxf(gg, 0.05f), 0.95f);
            float a  = 1.0f - gg * (1.0f - Avec[h]);
            float bb = gg * (acc[i][j + 1] + bias_h[h]);
            g_a[(size_t)m * DIM + h] = a;
            g_b[(size_t)m * DIM + h] = bb;
        }
    }
}

// ---------------------------------------------------------------------------
// Stage 2: sequential scan  h_t = a_t * h_{t-1} + b_t  per (batch, hidden)
// 4096 independent chains; coalesced across h.
// ---------------------------------------------------------------------------
__global__ void scan_kernel()
{
    const int tid = blockIdx.x * blockDim.x + threadIdx.x;  // 0..4095
    const int b = tid >> 9;
    const int h = tid & 511;
    const size_t base = ((size_t)b * SEQLEN) * DIM + h;
    const float* __restrict__ pa = g_a + base;
    const float* __restrict__ pb = g_b + base;
    float* __restrict__ ph = g_hs + base;

    float hcur = 0.0f;
    #pragma unroll 4
    for (int t = 0; t < SEQLEN; ++t) {
        const size_t off = (size_t)t * DIM;
        float a  = pa[off];
        float bb = pb[off];
        hcur = fmaf(a, hcur, bb);
        ph[off] = hcur;
    }
}

// ---------------------------------------------------------------------------
// Stage 3: y = (hs @ C^T + x @ D^T + bias_y) * scale   (M=32768, N=512)
// Twin-accumulate into one 8x8 tile (two K=512 mainloops).
// ---------------------------------------------------------------------------
__global__ __launch_bounds__(256) void stage3_kernel(
    const float* __restrict__ x,
    const float* __restrict__ C,
    const float* __restrict__ Dm,
    const float* __restrict__ bias_y,
    float* __restrict__ out)
{
    __shared__ float As[16][128];
    __shared__ float Ws[16][128];
    float acc[8][8];
    #pragma unroll
    for (int i = 0; i < 8; ++i)
        #pragma unroll
        for (int j = 0; j < 8; ++j) acc[i][j] = 0.f;

    const int row0 = blockIdx.y * 128;
    const int col0 = blockIdx.x * 128;
    gemm_mainloop(g_hs, C,  DIM, row0, col0, acc, As, Ws);
    gemm_mainloop(x,    Dm, DIM, row0, col0, acc, As, Ws);

    const float scale = 0.04419417382415922f;  // 1/sqrt(512)
    const int tx = threadIdx.x & 15;
    const int ty = threadIdx.x >> 4;
    const int cn = col0 + tx * 8;

    #pragma unroll
    for (int i = 0; i < 8; ++i) {
        const int m = row0 + ty * 8 + i;
        float4 o0, o1;
        o0.x = (acc[i][0] + bias_y[cn + 0]) * scale;
        o0.y = (acc[i][1] + bias_y[cn + 1]) * scale;
        o0.z = (acc[i][2] + bias_y[cn + 2]) * scale;
        o0.w = (acc[i][3] + bias_y[cn + 3]) * scale;
        o1.x = (acc[i][4] + bias_y[cn + 4]) * scale;
        o1.y = (acc[i][5] + bias_y[cn + 5]) * scale;
        o1.z = (acc[i][6] + bias_y[cn + 6]) * scale;
        o1.w = (acc[i][7] + bias_y[cn + 7]) * scale;
        *reinterpret_cast<float4*>(out + (size_t)m * DIM + cn + 0) = o0;
        *reinterpret_cast<float4*>(out + (size_t)m * DIM + cn + 4) = o1;
    }
}

// ---------------------------------------------------------------------------
extern "C" void kernel_launch(void* const* d_in, const int* in_sizes, int n_in,
                              void* d_out, int out_size)
{
    // metadata order: x, A, B, C, D, Wg, bias_h, bias_y
    const float* x      = (const float*)d_in[0];
    const float* Avec   = (const float*)d_in[1];
    const float* B      = (const float*)d_in[2];
    const float* C      = (const float*)d_in[3];
    const float* Dm     = (const float*)d_in[4];
    const float* Wg     = (const float*)d_in[5];
    const float* bias_h = (const float*)d_in[6];
    const float* bias_y = (const float*)d_in[7];
    float* out = (float*)d_out;

    // 1) interleaved weight [Wg;B] -> g_W1
    prep_w1_kernel<<<(1024 * DIM + 255) / 256, 256>>>(Wg, B);

    // 2) x @ W1^T + gate epilogue -> g_a, g_b   (grid: N=1024/128 x M/128)
    stage1_kernel<<<dim3(8, MROWS / 128), 256>>>(x, Avec, bias_h);

    // 3) sequential scan -> g_hs
    scan_kernel<<<32, 128>>>();

    // 4) (hs@C^T + x@D^T + bias_y)*scale -> out  (grid: N=512/128 x M/128)
    stage3_kernel<<<dim3(4, MROWS / 128), 256>>>(x, C, Dm, bias_y, out);
}

// round 3
// speedup vs baseline: 2.2912x; 2.2912x over previous
#include <cuda_runtime.h>
#include <math.h>

#define BATCH   8
#define SEQLEN  4096
#define DIM     512
#define KDIM    512
#define MROWS   (BATCH * SEQLEN)   // 32768
#define CHUNK   128
#define NCHUNK  (SEQLEN / CHUNK)   // 32

// ---- static scratch (no allocations allowed) ----
__device__ float g_a  [(size_t)MROWS * DIM];          // a_coef -> cumA (in place)
__device__ float g_b  [(size_t)MROWS * DIM];          // b_coef
__device__ float g_hs [(size_t)MROWS * DIM];          // local scan -> fixed scan
__device__ float g_W1 [1024 * DIM];                   // interleaved [Wg;B]
__device__ float g_Hin[BATCH * NCHUNK * DIM];         // chunk carry-in (512 KB)

// ---------------------------------------------------------------------------
__global__ void prep_w1_kernel(const float* __restrict__ Wg,
                               const float* __restrict__ B)
{
    int idx = blockIdx.x * blockDim.x + threadIdx.x;
    if (idx < 1024 * DIM) {
        int r = idx / DIM;
        int k = idx - r * DIM;
        int h = r >> 1;
        g_W1[idx] = (r & 1) ? B[h * DIM + k] : Wg[h * DIM + k];
    }
}

// ---------------------------------------------------------------------------
// Double-buffered SGEMM mainloop: acc[8][8] += A[row0:+128,:512] * W[col0:+128,:512]^T
// A,W row-major NT. BM=BN=128, BK=16, 256 threads, 8x8 microtile.
// Shared buffers: As/Ws are [32][132] (two 16-row buffers, +4 pad vs bank conflicts).
// ---------------------------------------------------------------------------
__device__ __forceinline__ void stash_tile(float (*S)[132], int r0, int m0,
                                           float4 v0, float4 v1)
{
    S[r0 + 0][m0] = v0.x; S[r0 + 1][m0] = v0.y;
    S[r0 + 2][m0] = v0.z; S[r0 + 3][m0] = v0.w;
    S[r0 + 0][m0 + 64] = v1.x; S[r0 + 1][m0 + 64] = v1.y;
    S[r0 + 2][m0 + 64] = v1.z; S[r0 + 3][m0 + 64] = v1.w;
}

__device__ __forceinline__ void gemm_tile_db(
    const float* __restrict__ A, const float* __restrict__ W,
    int row0, int col0, float acc[8][8],
    float (*As)[132], float (*Ws)[132])
{
    const int tid = threadIdx.x;
    const int tx  = tid & 15;
    const int ty  = tid >> 4;
    const int m0  = tid >> 2;       // 0..63
    const int kv  = tid & 3;        // which float4 within BK=16 row segment

    const float* gA = A + (size_t)(row0 + m0) * KDIM + kv * 4;
    const float* gW = W + (size_t)(col0 + m0) * KDIM + kv * 4;

    // prologue: load k0 = 0 tile
    float4 a0 = *(const float4*)(gA);
    float4 a1 = *(const float4*)(gA + (size_t)64 * KDIM);
    float4 w0 = *(const float4*)(gW);
    float4 w1 = *(const float4*)(gW + (size_t)64 * KDIM);

    int buf = 0;
    stash_tile(As, kv * 4, m0, a0, a1);
    stash_tile(Ws, kv * 4, m0, w0, w1);
    __syncthreads();

    for (int k0 = 16; ; k0 += 16) {
        const bool more = (k0 < KDIM);
        if (more) {
            a0 = *(const float4*)(gA + k0);
            a1 = *(const float4*)(gA + k0 + (size_t)64 * KDIM);
            w0 = *(const float4*)(gW + k0);
            w1 = *(const float4*)(gW + k0 + (size_t)64 * KDIM);
        }

        #pragma unroll
        for (int kk = 0; kk < 16; ++kk) {
            const float* ar = &As[buf + kk][ty * 8];
            const float* wr = &Ws[buf + kk][tx * 8];
            float4 af0 = *(const float4*)(ar);
            float4 af1 = *(const float4*)(ar + 4);
            float4 wf0 = *(const float4*)(wr);
            float4 wf1 = *(const float4*)(wr + 4);
            float af[8] = {af0.x, af0.y, af0.z, af0.w, af1.x, af1.y, af1.z, af1.w};
            float wf[8] = {wf0.x, wf0.y, wf0.z, wf0.w, wf1.x, wf1.y, wf1.z, wf1.w};
            #pragma unroll
            for (int i = 0; i < 8; ++i)
                #pragma unroll
                for (int j = 0; j < 8; ++j)
                    acc[i][j] = fmaf(af[i], wf[j], acc[i][j]);
        }
        if (!more) break;

        buf ^= 16;
        stash_tile(As, buf + kv * 4, m0, a0, a1);
        stash_tile(Ws, buf + kv * 4, m0, w0, w1);
        __syncthreads();
    }
    __syncthreads();   // smem safe for reuse by a following mainloop
}

// ---------------------------------------------------------------------------
// Stage 1: raw = x @ [Wg;B]^T (M=32768, N=1024, K=512); epilogue emits a,b coefs
// ---------------------------------------------------------------------------
__global__ __launch_bounds__(256) void stage1_kernel(
    const float* __restrict__ x,
    const float* __restrict__ Avec,
    const float* __restrict__ bias_h)
{
    __shared__ __align__(16) float As[32][132];
    __shared__ __align__(16) float Ws[32][132];
    float acc[8][8];
    #pragma unroll
    for (int i = 0; i < 8; ++i)
        #pragma unroll
        for (int j = 0; j < 8; ++j) acc[i][j] = 0.f;

    const int row0 = blockIdx.y * 128;
    const int col0 = blockIdx.x * 128;
    gemm_tile_db(x, g_W1, row0, col0, acc, As, Ws);

    const int tx = threadIdx.x & 15;
    const int ty = threadIdx.x >> 4;
    const int cn = col0 + tx * 8;   // even-aligned

    #pragma unroll
    for (int i = 0; i < 8; ++i) {
        const int m = row0 + ty * 8 + i;
        #pragma unroll
        for (int j = 0; j < 8; j += 2) {
            const int h = (cn + j) >> 1;
            float z  = acc[i][j];
            float gg = 1.0f / (1.0f + __expf(-z));
            gg = fminf(fmaxf(gg, 0.05f), 0.95f);
            float a  = 1.0f - gg * (1.0f - Avec[h]);
            float bb = gg * (acc[i][j + 1] + bias_h[h]);
            g_a[(size_t)m * DIM + h] = a;
            g_b[(size_t)m * DIM + h] = bb;
        }
    }
}

// ---------------------------------------------------------------------------
// Scan pass A: per-chunk local scan (h_in = 0) + cumulative product of a.
// g_hs <- local scan; g_a <- cumA (overwritten in place).
// grid = BATCH*NCHUNK blocks of 512 threads (one thread per h).
// ---------------------------------------------------------------------------
__global__ __launch_bounds__(512) void scan_local_kernel()
{
    const int bc = blockIdx.x;
    const int b  = bc / NCHUNK;
    const int c  = bc % NCHUNK;
    const int h  = threadIdx.x;
    const size_t base = ((size_t)b * SEQLEN + (size_t)c * CHUNK) * DIM + h;

    float hcur = 0.0f;
    float cum  = 1.0f;
    #pragma unroll 4
    for (int t = 0; t < CHUNK; ++t) {
        const size_t off = base + (size_t)t * DIM;
        float a  = g_a[off];
        float bb = g_b[off];
        hcur = fmaf(a, hcur, bb);
        cum *= a;
        g_hs[off] = hcur;
        g_a[off]  = cum;
    }
}

// ---------------------------------------------------------------------------
// Scan pass B: carry scan across chunks. h_in[c] = P[c-1]*h_in[c-1] + Q[c-1]
// P/Q read from last row of each chunk in g_a/g_hs. 8 blocks x 512 threads.
// ---------------------------------------------------------------------------
__global__ __launch_bounds__(512) void scan_carry_kernel()
{
    const int b = blockIdx.x;
    const int h = threadIdx.x;
    float hin = 0.0f;
    #pragma unroll
    for (int c = 0; c < NCHUNK; ++c) {
        g_Hin[((size_t)b * NCHUNK + c) * DIM + h] = hin;
        const size_t last = ((size_t)b * SEQLEN + (size_t)c * CHUNK + (CHUNK - 1)) * DIM + h;
        float P = g_a[last];
        float Q = g_hs[last];
        hin = fmaf(P, hin, Q);
    }
}

// ---------------------------------------------------------------------------
// Scan pass C: hs_true[t] = hs_local[t] + h_in[b,c] * cumA[t]   (vectorized)
// ---------------------------------------------------------------------------
__global__ __launch_bounds__(256) void scan_fixup_kernel()
{
    const size_t idx = (size_t)blockIdx.x * blockDim.x + threadIdx.x;  // float4 idx
    const int hv = (int)(idx & 127);       // DIM/4 = 128 float4 per row
    const int m  = (int)(idx >> 7);
    const int t  = m & (SEQLEN - 1);
    const int b  = m >> 12;
    const int c  = t >> 7;                 // t / CHUNK

    const size_t e = (size_t)m * DIM + hv * 4;
    float4 hin = *(const float4*)&g_Hin[((size_t)b * NCHUNK + c) * DIM + hv * 4];
    float4 cum = *(const float4*)&g_a[e];
    float4 hs  = *(float4*)&g_hs[e];
    hs.x = fmaf(hin.x, cum.x, hs.x);
    hs.y = fmaf(hin.y, cum.y, hs.y);
    hs.z = fmaf(hin.z, cum.z, hs.z);
    hs.w = fmaf(hin.w, cum.w, hs.w);
    *(float4*)&g_hs[e] = hs;
}

// ---------------------------------------------------------------------------
// Stage 3: y = (hs @ C^T + x @ D^T + bias_y) * scale
// ---------------------------------------------------------------------------
__global__ __launch_bounds__(256) void stage3_kernel(
    const float* __restrict__ x,
    const float* __restrict__ C,
    const float* __restrict__ Dm,
    const float* __restrict__ bias_y,
    float* __restrict__ out)
{
    __shared__ __align__(16) float As[32][132];
    __shared__ __align__(16) float Ws[32][132];
    float acc[8][8];
    #pragma unroll
    for (int i = 0; i < 8; ++i)
        #pragma unroll
        for (int j = 0; j < 8; ++j) acc[i][j] = 0.f;

    const int row0 = blockIdx.y * 128;
    const int col0 = blockIdx.x * 128;
    gemm_tile_db(g_hs, C,  row0, col0, acc, As, Ws);
    gemm_tile_db(x,    Dm, row0, col0, acc, As, Ws);

    const float scale = 0.04419417382415922f;  // 1/sqrt(512)
    const int tx = threadIdx.x & 15;
    const int ty = threadIdx.x >> 4;
    const int cn = col0 + tx * 8;

    #pragma unroll
    for (int i = 0; i < 8; ++i) {
        const int m = row0 + ty * 8 + i;
        float4 o0, o1;
        o0.x = (acc[i][0] + bias_y[cn + 0]) * scale;
        o0.y = (acc[i][1] + bias_y[cn + 1]) * scale;
        o0.z = (acc[i][2] + bias_y[cn + 2]) * scale;
        o0.w = (acc[i][3] + bias_y[cn + 3]) * scale;
        o1.x = (acc[i][4] + bias_y[cn + 4]) * scale;
        o1.y = (acc[i][5] + bias_y[cn + 5]) * scale;
        o1.z = (acc[i][6] + bias_y[cn + 6]) * scale;
        o1.w = (acc[i][7] + bias_y[cn + 7]) * scale;
        *reinterpret_cast<float4*>(out + (size_t)m * DIM + cn + 0) = o0;
        *reinterpret_cast<float4*>(out + (size_t)m * DIM + cn + 4) = o1;
    }
}

// ---------------------------------------------------------------------------
extern "C" void kernel_launch(void* const* d_in, const int* in_sizes, int n_in,
                              void* d_out, int out_size)
{
    const float* x      = (const float*)d_in[0];
    const float* Avec   = (const float*)d_in[1];
    const float* B      = (const float*)d_in[2];
    const float* C      = (const float*)d_in[3];
    const float* Dm     = (const float*)d_in[4];
    const float* Wg     = (const float*)d_in[5];
    const float* bias_h = (const float*)d_in[6];
    const float* bias_y = (const float*)d_in[7];
    float* out = (float*)d_out;

    prep_w1_kernel<<<(1024 * DIM + 255) / 256, 256>>>(Wg, B);

    stage1_kernel<<<dim3(8, MROWS / 128), 256>>>(x, Avec, bias_h);

    scan_local_kernel<<<BATCH * NCHUNK, 512>>>();
    scan_carry_kernel<<<BATCH, 512>>>();
    scan_fixup_kernel<<<(MROWS * (DIM / 4)) / 256, 256>>>();

    stage3_kernel<<<dim3(4, MROWS / 128), 256>>>(x, C, Dm, bias_y, out);
}

// round 5
// speedup vs baseline: 5.1619x; 2.2529x over previous
#include <cuda_runtime.h>
#include <cuda_bf16.h>
#include <math.h>
#include <stdint.h>

#define BATCH   8
#define SEQLEN  4096
#define DIM     512
#define MROWS   (BATCH * SEQLEN)   // 32768
#define CHUNK   128
#define NCHUNK  (SEQLEN / CHUNK)   // 32

// ================= static scratch =================
__device__ float g_a  [(size_t)MROWS * DIM];
__device__ float g_b  [(size_t)MROWS * DIM];
__device__ float g_hs [(size_t)MROWS * DIM];
__device__ float g_Hin[BATCH * NCHUNK * DIM];

// bf16 split operands. A3 = [hs | x] : 32768 x 1024
__device__ __align__(16) __nv_bfloat16 g_A3hi[(size_t)MROWS * 1024];
__device__ __align__(16) __nv_bfloat16 g_A3lo[(size_t)MROWS * 1024];
__device__ __align__(16) __nv_bfloat16 g_W1hi[1024 * 512];   // interleaved [Wg;B]
__device__ __align__(16) __nv_bfloat16 g_W1lo[1024 * 512];
__device__ __align__(16) __nv_bfloat16 g_W3hi[512 * 1024];   // [C | D]
__device__ __align__(16) __nv_bfloat16 g_W3lo[512 * 1024];

// ================= PTX helpers (family-safe: sm_80+ features only) ========
__device__ __forceinline__ uint32_t smem_u32(const void* p) {
    uint32_t a;
    asm("{ .reg .u64 t; cvta.to.shared.u64 t, %1; cvt.u32.u64 %0, t; }"
        : "=r"(a) : "l"(p));
    return a;
}
__device__ __forceinline__ void cp16(uint32_t s, const void* g) {
    asm volatile("cp.async.cg.shared.global [%0], [%1], 16;"
                 :: "r"(s), "l"(__cvta_generic_to_global(g)) : "memory");
}
#define CP_COMMIT() asm volatile("cp.async.commit_group;" ::: "memory")
#define CP_WAIT(n)  asm volatile("cp.async.wait_group %0;" :: "n"(n) : "memory")

#define LDSM4(r0, r1, r2, r3, addr) \
    asm volatile("ldmatrix.sync.aligned.m8n8.x4.shared.b16 {%0,%1,%2,%3}, [%4];" \
                 : "=r"(r0), "=r"(r1), "=r"(r2), "=r"(r3) : "r"(addr))

#define MMA16816(c, a, b0, b1) \
    asm volatile("mma.sync.aligned.m16n8k16.row.col.f32.bf16.bf16.f32 " \
                 "{%0,%1,%2,%3}, {%4,%5,%6,%7}, {%8,%9}, {%0,%1,%2,%3};" \
                 : "+f"((c)[0]), "+f"((c)[1]), "+f"((c)[2]), "+f"((c)[3]) \
                 : "r"((a)[0]), "r"((a)[1]), "r"((a)[2]), "r"((a)[3]), \
                   "r"(b0), "r"(b1))

// smem tile geometry: 128 rows x 32 bf16 data, row stride 80B (conflict-free
// for ldmatrix: 80*r mod 128 covers all eight 16B slots over r=0..7).
#define T_STRIDE 80
#define T_BYTES  (128 * T_STRIDE)          // 10240
#define BUF_BYTES (4 * T_BYTES)            // Ahi,Alo,Whi,Wlo = 40960
#define SMEM_REQ  (2 * BUF_BYTES)          // 81920 (double buffer)

// ================= bf16 split =================
__device__ __forceinline__ void bsplit(float v, __nv_bfloat16& hi, __nv_bfloat16& lo) {
    hi = __float2bfloat16_rn(v);
    lo = __float2bfloat16_rn(v - __bfloat162float(hi));
}

// =======================================================================
// conv kernels
// =======================================================================
__global__ void conv_w_kernel(const float* __restrict__ Wg, const float* __restrict__ B,
                              const float* __restrict__ C,  const float* __restrict__ D)
{
    int idx = blockIdx.x * blockDim.x + threadIdx.x;
    if (idx < 1024 * 512) {
        int r = idx >> 9, k = idx & 511, h = r >> 1;
        float v = (r & 1) ? B[h * 512 + k] : Wg[h * 512 + k];
        __nv_bfloat16 hi, lo; bsplit(v, hi, lo);
        g_W1hi[idx] = hi; g_W1lo[idx] = lo;
    } else {
        int j = idx - 1024 * 512;
        int n = j >> 10, k = j & 1023;
        float v = (k < 512) ? C[n * 512 + k] : D[n * 512 + k - 512];
        __nv_bfloat16 hi, lo; bsplit(v, hi, lo);
        g_W3hi[j] = hi; g_W3lo[j] = lo;
    }
}

__global__ void conv_x_kernel(const float* __restrict__ x)
{
    size_t idx = (size_t)blockIdx.x * blockDim.x + threadIdx.x;   // float4 idx
    int cv = (int)(idx & 127);
    int m  = (int)(idx >> 7);
    float4 v = *(const float4*)&x[(size_t)m * 512 + cv * 4];
    __nv_bfloat16 h0,l0,h1,l1,h2,l2,h3,l3;
    bsplit(v.x,h0,l0); bsplit(v.y,h1,l1); bsplit(v.z,h2,l2); bsplit(v.w,h3,l3);
    size_t o = (size_t)m * 1024 + 512 + cv * 4;
    *(__nv_bfloat162*)&g_A3hi[o]     = __halves2bfloat162(h0, h1);
    *(__nv_bfloat162*)&g_A3hi[o + 2] = __halves2bfloat162(h2, h3);
    *(__nv_bfloat162*)&g_A3lo[o]     = __halves2bfloat162(l0, l1);
    *(__nv_bfloat162*)&g_A3lo[o + 2] = __halves2bfloat162(l2, l3);
}

// =======================================================================
// HMMA mainloop pieces
// =======================================================================
__device__ __forceinline__ void issue_chunk(
    uint32_t tb, int tid, int k0,
    const __nv_bfloat16* __restrict__ Ahi, const __nv_bfloat16* __restrict__ Alo, int lda,
    const __nv_bfloat16* __restrict__ Whi, const __nv_bfloat16* __restrict__ Wlo, int ldw)
{
    #pragma unroll
    for (int i = 0; i < 2; ++i) {
        int idx = i * 256 + tid;
        int r = idx >> 2, ch = idx & 3;
        uint32_t so = (uint32_t)(r * T_STRIDE + ch * 16);
        int go = k0 + ch * 8;
        cp16(tb +               so, Ahi + (size_t)r * lda + go);
        cp16(tb +     T_BYTES + so, Alo + (size_t)r * lda + go);
        cp16(tb + 2 * T_BYTES + so, Whi + (size_t)r * ldw + go);
        cp16(tb + 3 * T_BYTES + so, Wlo + (size_t)r * ldw + go);
    }
    CP_COMMIT();
}

template<int NC>
__device__ __forceinline__ void hmma_mainloop(
    uint32_t sb,
    const __nv_bfloat16* __restrict__ Ahi, const __nv_bfloat16* __restrict__ Alo, int lda,
    const __nv_bfloat16* __restrict__ Whi, const __nv_bfloat16* __restrict__ Wlo, int ldw,
    float acc[2][8][4])
{
    const int tid  = threadIdx.x;
    const int wid  = tid >> 5, lane = tid & 31;
    const int wm   = (wid >> 1) * 32;       // warp m offset (0..96)
    const int wn   = (wid & 1) * 64;        // warp n offset (0 or 64)
    // ldmatrix lane-address selectors
    const uint32_t aSel = (uint32_t)((lane & 15) * T_STRIDE + (lane >> 4) * 16);
    const uint32_t bSel = (uint32_t)((((lane >> 4) << 3) + (lane & 7)) * T_STRIDE
                                     + ((lane >> 3) & 1) * 16);

    issue_chunk(sb,             tid, 0,  Ahi, Alo, lda, Whi, Wlo, ldw);
    issue_chunk(sb + BUF_BYTES, tid, 32, Ahi, Alo, lda, Whi, Wlo, ldw);

    #pragma unroll 1
    for (int c = 0; c < NC; ++c) {
        if (c + 1 == NC) { CP_WAIT(0); } else { CP_WAIT(1); }
        __syncthreads();

        const uint32_t tb = sb + (uint32_t)(c & 1) * BUF_BYTES;
        const uint32_t At = tb + (uint32_t)wm * T_STRIDE + aSel;
        const uint32_t Wt = tb + 2 * T_BYTES + (uint32_t)wn * T_STRIDE + bSel;

        #pragma unroll
        for (int kk = 0; kk < 2; ++kk) {
            const uint32_t ko = kk * 32;    // 16 bf16 = 32B per k16 step
            uint32_t ah[2][4], al[2][4];
            #pragma unroll
            for (int mb = 0; mb < 2; ++mb) {
                LDSM4(ah[mb][0], ah[mb][1], ah[mb][2], ah[mb][3],
                      At + mb * (16 * T_STRIDE) + ko);
                LDSM4(al[mb][0], al[mb][1], al[mb][2], al[mb][3],
                      At + T_BYTES + mb * (16 * T_STRIDE) + ko);
            }
            #pragma unroll
            for (int nb = 0; nb < 4; ++nb) {
                uint32_t bh[4], bl[4];
                LDSM4(bh[0], bh[1], bh[2], bh[3], Wt + nb * (16 * T_STRIDE) + ko);
                LDSM4(bl[0], bl[1], bl[2], bl[3], Wt + T_BYTES + nb * (16 * T_STRIDE) + ko);
                #pragma unroll
                for (int mb = 0; mb < 2; ++mb) {
                    MMA16816(acc[mb][2 * nb],     ah[mb], bh[0], bh[1]);
                    MMA16816(acc[mb][2 * nb],     ah[mb], bl[0], bl[1]);
                    MMA16816(acc[mb][2 * nb],     al[mb], bh[0], bh[1]);
                    MMA16816(acc[mb][2 * nb + 1], ah[mb], bh[2], bh[3]);
                    MMA16816(acc[mb][2 * nb + 1], ah[mb], bl[2], bl[3]);
                    MMA16816(acc[mb][2 * nb + 1], al[mb], bh[2], bh[3]);
                }
            }
        }
        __syncthreads();
        if (c + 2 < NC)
            issue_chunk(sb + (uint32_t)(c & 1) * BUF_BYTES, tid, (c + 2) * 32,
                        Ahi, Alo, lda, Whi, Wlo, ldw);
    }
}

// =======================================================================
// Stage 1: raw = x @ W1^T (M=32768, N=1024, K=512) -> a,b coefs
// =======================================================================
__global__ __launch_bounds__(256, 2)
void hmma_stage1_kernel(const float* __restrict__ Avec,
                        const float* __restrict__ bias_h)
{
    extern __shared__ __align__(16) char smem[];
    const uint32_t sb = smem_u32(smem);

    float acc[2][8][4];
    #pragma unroll
    for (int i = 0; i < 2; ++i)
        #pragma unroll
        for (int j = 0; j < 8; ++j)
            #pragma unroll
            for (int q = 0; q < 4; ++q) acc[i][j][q] = 0.f;

    const int row0 = blockIdx.y * 128;
    const int col0 = blockIdx.x * 128;

    hmma_mainloop<16>(sb,
                      g_A3hi + 512 + (size_t)row0 * 1024,
                      g_A3lo + 512 + (size_t)row0 * 1024, 1024,
                      g_W1hi + (size_t)col0 * 512,
                      g_W1lo + (size_t)col0 * 512, 512,
                      acc);

    // -------- epilogue: gate math in-lane (pair cols), smem restage --------
    const int tid = threadIdx.x, wid = tid >> 5, lane = tid & 31;
    const int wm = (wid >> 1) * 32, wn = (wid & 1) * 64;
    const int g = lane >> 2, tig = lane & 3;
    const int hbase = col0 >> 1;

    float* sA = (float*)smem;              // [128][65]
    float* sB = sA + 128 * 65;             // [128][65]

    #pragma unroll
    for (int mb = 0; mb < 2; ++mb) {
        #pragma unroll
        for (int j = 0; j < 8; ++j) {
            int h_loc = (wn + (j >> 1) * 16 + (j & 1) * 8 + 2 * tig) >> 1;
            int hg = hbase + h_loc;
            float Ah = Avec[hg], Bh = bias_h[hg];
            int m0 = wm + mb * 16 + g;

            float z0 = acc[mb][j][0], x0 = acc[mb][j][1];
            float g0 = 1.0f / (1.0f + __expf(-z0));
            g0 = fminf(fmaxf(g0, 0.05f), 0.95f);
            sA[m0 * 65 + h_loc] = 1.0f - g0 * (1.0f - Ah);
            sB[m0 * 65 + h_loc] = g0 * (x0 + Bh);

            float z1 = acc[mb][j][2], x1 = acc[mb][j][3];
            float g1 = 1.0f / (1.0f + __expf(-z1));
            g1 = fminf(fmaxf(g1, 0.05f), 0.95f);
            sA[(m0 + 8) * 65 + h_loc] = 1.0f - g1 * (1.0f - Ah);
            sB[(m0 + 8) * 65 + h_loc] = g1 * (x1 + Bh);
        }
    }
    __syncthreads();

    const int hh = tid & 63, rg = tid >> 6;
    #pragma unroll
    for (int r = 0; r < 32; ++r) {
        int row = rg * 32 + r;
        size_t gb = (size_t)(row0 + row) * DIM + hbase + hh;
        g_a[gb] = sA[row * 65 + hh];
        g_b[gb] = sB[row * 65 + hh];
    }
}

// =======================================================================
// Stage 3: y = (hs@C^T + x@D^T + bias_y)*scale, K=1024 fused GEMM
// =======================================================================
__global__ __launch_bounds__(256, 2)
void hmma_stage3_kernel(const float* __restrict__ bias_y, float* __restrict__ out)
{
    extern __shared__ __align__(16) char smem[];
    const uint32_t sb = smem_u32(smem);

    float acc[2][8][4];
    #pragma unroll
    for (int i = 0; i < 2; ++i)
        #pragma unroll
        for (int j = 0; j < 8; ++j)
            #pragma unroll
            for (int q = 0; q < 4; ++q) acc[i][j][q] = 0.f;

    const int row0 = blockIdx.y * 128;
    const int col0 = blockIdx.x * 128;

    hmma_mainloop<32>(sb,
                      g_A3hi + (size_t)row0 * 1024,
                      g_A3lo + (size_t)row0 * 1024, 1024,
                      g_W3hi + (size_t)col0 * 1024,
                      g_W3lo + (size_t)col0 * 1024, 1024,
                      acc);

    const int tid = threadIdx.x, wid = tid >> 5, lane = tid & 31;
    const int wm = (wid >> 1) * 32, wn = (wid & 1) * 64;
    const int g = lane >> 2, tig = lane & 3;
    const float scale = 0.04419417382415922f;   // 1/sqrt(512)

    float* sY = (float*)smem;                   // [128][129]

    #pragma unroll
    for (int mb = 0; mb < 2; ++mb) {
        #pragma unroll
        for (int j = 0; j < 8; ++j) {
            int n0 = wn + (j >> 1) * 16 + (j & 1) * 8 + 2 * tig;
            float by0 = bias_y[col0 + n0], by1 = bias_y[col0 + n0 + 1];
            int m0 = wm + mb * 16 + g;
            sY[m0 * 129 + n0]           = (acc[mb][j][0] + by0) * scale;
            sY[m0 * 129 + n0 + 1]       = (acc[mb][j][1] + by1) * scale;
            sY[(m0 + 8) * 129 + n0]     = (acc[mb][j][2] + by0) * scale;
            sY[(m0 + 8) * 129 + n0 + 1] = (acc[mb][j][3] + by1) * scale;
        }
    }
    __syncthreads();

    const int nn = tid & 127, rg = tid >> 7;
    #pragma unroll
    for (int r = 0; r < 64; ++r) {
        int row = rg * 64 + r;
        out[(size_t)(row0 + row) * DIM + col0 + nn] = sY[row * 129 + nn];
    }
}

// =======================================================================
// scan passes (fp32)
// =======================================================================
__global__ __launch_bounds__(512) void scan_local_kernel()
{
    const int bc = blockIdx.x;
    const int b  = bc / NCHUNK;
    const int c  = bc % NCHUNK;
    const int h  = threadIdx.x;
    const size_t base = ((size_t)b * SEQLEN + (size_t)c * CHUNK) * DIM + h;

    float hcur = 0.0f, cum = 1.0f;
    #pragma unroll 4
    for (int t = 0; t < CHUNK; ++t) {
        const size_t off = base + (size_t)t * DIM;
        float a  = g_a[off];
        float bb = g_b[off];
        hcur = fmaf(a, hcur, bb);
        cum *= a;
        g_hs[off] = hcur;
        g_a[off]  = cum;
    }
}

__global__ __launch_bounds__(512) void scan_carry_kernel()
{
    const int b = blockIdx.x;
    const int h = threadIdx.x;
    float hin = 0.0f;
    #pragma unroll
    for (int c = 0; c < NCHUNK; ++c) {
        g_Hin[((size_t)b * NCHUNK + c) * DIM + h] = hin;
        const size_t last = ((size_t)b * SEQLEN + (size_t)c * CHUNK + (CHUNK - 1)) * DIM + h;
        hin = fmaf(g_a[last], hin, g_hs[last]);
    }
}

// fixup: hs_true = local + hin*cum -> bf16 hi/lo into A3 columns [0,512)
__global__ __launch_bounds__(256) void scan_fixup_kernel()
{
    const size_t idx = (size_t)blockIdx.x * blockDim.x + threadIdx.x;
    const int cv = (int)(idx & 127);
    const int m  = (int)(idx >> 7);
    const int t  = m & (SEQLEN - 1);
    const int b  = m >> 12;
    const int c  = t >> 7;

    const size_t e = (size_t)m * DIM + cv * 4;
    float4 hin = *(const float4*)&g_Hin[((size_t)b * NCHUNK + c) * DIM + cv * 4];
    float4 cum = *(const float4*)&g_a[e];
    float4 loc = *(const float4*)&g_hs[e];
    float v0 = fmaf(hin.x, cum.x, loc.x);
    float v1 = fmaf(hin.y, cum.y, loc.y);
    float v2 = fmaf(hin.z, cum.z, loc.z);
    float v3 = fmaf(hin.w, cum.w, loc.w);

    __nv_bfloat16 h0,l0,h1,l1,h2,l2,h3,l3;
    bsplit(v0,h0,l0); bsplit(v1,h1,l1); bsplit(v2,h2,l2); bsplit(v3,h3,l3);
    size_t o = (size_t)m * 1024 + cv * 4;
    *(__nv_bfloat162*)&g_A3hi[o]     = __halves2bfloat162(h0, h1);
    *(__nv_bfloat162*)&g_A3hi[o + 2] = __halves2bfloat162(h2, h3);
    *(__nv_bfloat162*)&g_A3lo[o]     = __halves2bfloat162(l0, l1);
    *(__nv_bfloat162*)&g_A3lo[o + 2] = __halves2bfloat162(l2, l3);
}

// =======================================================================
extern "C" void kernel_launch(void* const* d_in, const int* in_sizes, int n_in,
                              void* d_out, int out_size)
{
    const float* x      = (const float*)d_in[0];
    const float* Avec   = (const float*)d_in[1];
    const float* B      = (const float*)d_in[2];
    const float* C      = (const float*)d_in[3];
    const float* Dm     = (const float*)d_in[4];
    const float* Wg     = (const float*)d_in[5];
    const float* bias_h = (const float*)d_in[6];
    const float* bias_y = (const float*)d_in[7];
    float* out = (float*)d_out;

    cudaFuncSetAttribute(hmma_stage1_kernel,
                         cudaFuncAttributeMaxDynamicSharedMemorySize, SMEM_REQ);
    cudaFuncSetAttribute(hmma_stage3_kernel,
                         cudaFuncAttributeMaxDynamicSharedMemorySize, SMEM_REQ);

    conv_w_kernel<<<(1024 * 512 + 512 * 1024) / 256, 256>>>(Wg, B, C, Dm);
    conv_x_kernel<<<(MROWS * (DIM / 4)) / 256, 256>>>(x);

    hmma_stage1_kernel<<<dim3(8, MROWS / 128), 256, SMEM_REQ>>>(Avec, bias_h);

    scan_local_kernel<<<BATCH * NCHUNK, 512>>>();
    scan_carry_kernel<<<BATCH, 512>>>();
    scan_fixup_kernel<<<(MROWS * (DIM / 4)) / 256, 256>>>();

    hmma_stage3_kernel<<<dim3(4, MROWS / 128), 256, SMEM_REQ>>>(bias_y, out);
}